// round 8
// baseline (speedup 1.0000x reference)
#include <cuda_runtime.h>
#include <cuda_bf16.h>
#include <math.h>
#include <stdint.h>

#define B_   2
#define T_   2048
#define D_   1024
#define NH_  16
#define HD_  64
#define BT_  (B_*T_)      // 4096
#define NDH_ (NH_*HD_)    // 1024
#define K2_  (D_/2)       // 512

// Scratch (allocation-free: __device__ globals)
__device__ float g_q[(size_t)B_*NH_*T_*HD_];     // [b,n,t,h]
__device__ float g_k[(size_t)B_*NH_*T_*HD_];     // [b,n,t,h]
__device__ float g_v[(size_t)B_*NH_*T_*HD_];     // [b,n,t,h]

// attention output, prepacked bf16 hi/lo pairs along (n,h): [4096][512] u32
__device__ uint32_t g_oh[(size_t)BT_*K2_], g_ol[(size_t)BT_*K2_];

// prepacked weights: [n_out][k/2] u32 = (bf16 even-k, bf16 odd-k)
__device__ uint32_t g_wq_hi[(size_t)NDH_*K2_], g_wq_lo[(size_t)NDH_*K2_];
__device__ uint32_t g_wk_hi[(size_t)NDH_*K2_], g_wk_lo[(size_t)NDH_*K2_];
__device__ uint32_t g_wv_hi[(size_t)NDH_*K2_], g_wv_lo[(size_t)NDH_*K2_];
__device__ uint32_t g_wp_hi[(size_t)D_*K2_],   g_wp_lo[(size_t)D_*K2_];

// ---------------------------------------------------------------------------
// helpers
// ---------------------------------------------------------------------------
__device__ __forceinline__ uint32_t f2tf32(float x) {
    uint32_t r;
    asm("cvt.rna.tf32.f32 %0, %1;" : "=r"(r) : "f"(x));
    return r;
}

__device__ __forceinline__ float ex2(float x) {
    float r;
    asm("ex2.approx.f32 %0, %1;" : "=f"(r) : "f"(x));
    return r;
}

__device__ __forceinline__ uint32_t smaddr(const void* p) {
    return (uint32_t)__cvta_generic_to_shared(p);
}

__device__ __forceinline__ void ldsm4(uint32_t& r0, uint32_t& r1,
                                      uint32_t& r2, uint32_t& r3, uint32_t a) {
    asm volatile("ldmatrix.sync.aligned.m8n8.x4.shared.b16 {%0,%1,%2,%3}, [%4];"
                 : "=r"(r0), "=r"(r1), "=r"(r2), "=r"(r3) : "r"(a));
}

__device__ __forceinline__ void mma_tf32(float* c,
                                         uint32_t a0, uint32_t a1, uint32_t a2, uint32_t a3,
                                         uint32_t b0, uint32_t b1) {
    asm volatile("mma.sync.aligned.m16n8k8.row.col.f32.tf32.tf32.f32 "
                 "{%0,%1,%2,%3}, {%4,%5,%6,%7}, {%8,%9}, {%0,%1,%2,%3};"
                 : "+f"(c[0]), "+f"(c[1]), "+f"(c[2]), "+f"(c[3])
                 : "r"(a0), "r"(a1), "r"(a2), "r"(a3), "r"(b0), "r"(b1));
}

__device__ __forceinline__ void mma_bf16(float* c,
                                         uint32_t a0, uint32_t a1, uint32_t a2, uint32_t a3,
                                         uint32_t b0, uint32_t b1) {
    asm volatile("mma.sync.aligned.m16n8k16.row.col.f32.bf16.bf16.f32 "
                 "{%0,%1,%2,%3}, {%4,%5,%6,%7}, {%8,%9}, {%0,%1,%2,%3};"
                 : "+f"(c[0]), "+f"(c[1]), "+f"(c[2]), "+f"(c[3])
                 : "r"(a0), "r"(a1), "r"(a2), "r"(a3), "r"(b0), "r"(b1));
}

// split two fp32 (even,odd along k) into packed bf16x2 hi and lo parts
__device__ __forceinline__ void split2(float e, float o, uint32_t& hi, uint32_t& lo) {
    __nv_bfloat162 h = __floats2bfloat162_rn(e, o);
    float he = __low2float(h), ho = __high2float(h);
    __nv_bfloat162 l = __floats2bfloat162_rn(e - he, o - ho);
    hi = *reinterpret_cast<uint32_t*>(&h);
    lo = *reinterpret_cast<uint32_t*>(&l);
}

// ---------------------------------------------------------------------------
// Prepack QKV weights W [K][N] fp32 -> hi/lo [N][K/2] u32.  z selects q/k/v.
// ---------------------------------------------------------------------------
__global__ void prepack_wqkv_kernel(const float* __restrict__ Wq,
                                    const float* __restrict__ Wk,
                                    const float* __restrict__ Wv)
{
    const int z = blockIdx.z;
    const float* W = (z == 0) ? Wq : (z == 1) ? Wk : Wv;
    uint32_t* hi = (z == 0) ? g_wq_hi : (z == 1) ? g_wk_hi : g_wv_hi;
    uint32_t* lo = (z == 0) ? g_wq_lo : (z == 1) ? g_wk_lo : g_wv_lo;
    int idx = blockIdx.x * blockDim.x + threadIdx.x;
    if (idx >= NDH_ * K2_) return;
    int kp = idx & (K2_ - 1);
    int n  = idx >> 9;
    float e = W[(size_t)(2 * kp) * NDH_ + n];
    float o = W[(size_t)(2 * kp + 1) * NDH_ + n];
    uint32_t h, l;
    split2(e, o, h, l);
    hi[(size_t)n * K2_ + kp] = h;
    lo[(size_t)n * K2_ + kp] = l;
}

// ---------------------------------------------------------------------------
// Prepack w_projection [N, D, H] -> hi/lo [d][(n,h)/2] u32
// ---------------------------------------------------------------------------
__global__ void prepack_wpt_kernel(const float* __restrict__ wp)
{
    int idx = blockIdx.x * blockDim.x + threadIdx.x;
    if (idx >= D_ * K2_) return;
    int kp = idx & (K2_ - 1);       // n*32 + hp
    int d  = idx >> 9;
    int n  = kp >> 5;
    int hp = kp & 31;
    const float* base = wp + ((size_t)n * D_ + d) * HD_ + 2 * hp;
    float e = base[0], o = base[1];
    uint32_t h, l;
    split2(e, o, h, l);
    g_wp_hi[(size_t)d * K2_ + kp] = h;
    g_wp_lo[(size_t)d * K2_ + kp] = l;
}

// ---------------------------------------------------------------------------
// bf16-split tensor-core GEMM with ldmatrix fragments.
// A: fp32 [M,K] (APACKED=false) or hi/lo [M][K/2] u32 (APACKED=true).
// B: prepacked hi/lo [N][K/2] u32.
// 128x128 block tile, BK=16 (8 kpairs), 8 warps (2 M x 4 N), double-buffered.
// smem tiles row-major [row][kpair], row stride 12 u32 (conflict-free LDSM).
// MODE 0: C -> [B, N, T, H];  MODE 1: C -> [M, Ncols] row-major.
// ---------------------------------------------------------------------------
template<int MODE, bool APACKED>
__device__ __forceinline__ void gemm_core(const float* __restrict__ A,
                                          const uint32_t* __restrict__ Ahi,
                                          const uint32_t* __restrict__ Alo,
                                          const uint32_t* __restrict__ Bhi,
                                          const uint32_t* __restrict__ Blo,
                                          const float* __restrict__ bias,
                                          float* __restrict__ C,
                                          int M, int K, int Ncols)
{
    __shared__ uint32_t AsHi[2][128 * 12];
    __shared__ uint32_t AsLo[2][128 * 12];
    __shared__ uint32_t BsHi[2][128 * 12];
    __shared__ uint32_t BsLo[2][128 * 12];

    const int tid  = threadIdx.x;
    const int warp = tid >> 5;
    const int lane = tid & 31;
    const int g    = lane >> 2;
    const int tig  = lane & 3;
    const int wm   = warp >> 2;   // 0..1  (64 rows each)
    const int wn   = warp & 3;    // 0..3  (32 cols each)
    const int m0   = blockIdx.y * 128;
    const int n0   = blockIdx.x * 128;
    const int Kp   = K >> 1;

    const int lrow  = tid >> 1;          // 0..127 (row for both A and B loads)
    const int lhalf = tid & 1;           // kpair half: 0 or 1 (4 kpairs each)

    // ldmatrix per-lane offsets (units: u32 within a row-stride-12 tile)
    const int arow = (lane & 7) + ((lane >> 3) & 1) * 8;   // A-type
    const int akp  = (lane >> 4) * 4;
    const int brow = (lane & 7) + ((lane >> 4) & 1) * 8;   // B-type
    const int bkp  = ((lane >> 3) & 1) * 4;

    const uint32_t ash = smaddr(AsHi), asl = smaddr(AsLo);
    const uint32_t bsh = smaddr(BsHi), bsl = smaddr(BsLo);
    const uint32_t a_fo = ((arow) * 12 + akp) * 4;     // fragment lane offset
    const uint32_t b_fo = ((brow) * 12 + bkp) * 4;

    float acc[4][4][4];
    #pragma unroll
    for (int i = 0; i < 4; i++)
        #pragma unroll
        for (int j = 0; j < 4; j++)
            #pragma unroll
            for (int e = 0; e < 4; e++)
                acc[i][j][e] = 0.0f;

    float4 ar0, ar1;
    uint4  arh, arl;
    uint4  brh, brl;

    auto gload = [&](int k0) {
        if (APACKED) {
            const size_t aoff = (size_t)(m0 + lrow) * Kp + (k0 >> 1) + lhalf * 4;
            arh = *(const uint4*)(Ahi + aoff);
            arl = *(const uint4*)(Alo + aoff);
        } else {
            const float4* a4 = (const float4*)(A + (size_t)(m0 + lrow) * K + k0 + lhalf * 8);
            ar0 = a4[0];
            ar1 = a4[1];
        }
        const size_t boff = (size_t)(n0 + lrow) * Kp + (k0 >> 1) + lhalf * 4;
        brh = *(const uint4*)(Bhi + boff);
        brl = *(const uint4*)(Blo + boff);
    };

    auto sstore = [&](int st) {
        const int soff = lrow * 12 + lhalf * 4;
        if (APACKED) {
            *(uint4*)&AsHi[st][soff] = arh;
            *(uint4*)&AsLo[st][soff] = arl;
        } else {
            uint4 hh, ll;
            split2(ar0.x, ar0.y, hh.x, ll.x);
            split2(ar0.z, ar0.w, hh.y, ll.y);
            split2(ar1.x, ar1.y, hh.z, ll.z);
            split2(ar1.z, ar1.w, hh.w, ll.w);
            *(uint4*)&AsHi[st][soff] = hh;
            *(uint4*)&AsLo[st][soff] = ll;
        }
        *(uint4*)&BsHi[st][soff] = brh;
        *(uint4*)&BsLo[st][soff] = brl;
    };

    auto compute = [&](int st) {
        const uint32_t sto = st * (128 * 12 * 4);
        // B fragments: 4 nt tiles via 2x (hi,lo) LDSM.x4
        uint32_t bh[4][2], bl[4][2];
        #pragma unroll
        for (int nt2 = 0; nt2 < 2; nt2++) {
            const uint32_t ro = (wn * 32 + nt2 * 16) * 12 * 4;
            ldsm4(bh[nt2*2][0], bh[nt2*2][1], bh[nt2*2+1][0], bh[nt2*2+1][1],
                  bsh + sto + ro + b_fo);
            ldsm4(bl[nt2*2][0], bl[nt2*2][1], bl[nt2*2+1][0], bl[nt2*2+1][1],
                  bsl + sto + ro + b_fo);
        }
        #pragma unroll
        for (int mt = 0; mt < 4; mt++) {
            const uint32_t ro = (wm * 64 + mt * 16) * 12 * 4;
            uint32_t ah0, ah1, ah2, ah3, al0, al1, al2, al3;
            ldsm4(ah0, ah1, ah2, ah3, ash + sto + ro + a_fo);
            ldsm4(al0, al1, al2, al3, asl + sto + ro + a_fo);
            #pragma unroll
            for (int nt = 0; nt < 4; nt++) {
                mma_bf16(acc[mt][nt], ah0, ah1, ah2, ah3, bh[nt][0], bh[nt][1]);
                mma_bf16(acc[mt][nt], ah0, ah1, ah2, ah3, bl[nt][0], bl[nt][1]);
                mma_bf16(acc[mt][nt], al0, al1, al2, al3, bh[nt][0], bh[nt][1]);
            }
        }
    };

    // prologue
    gload(0);
    sstore(0);
    __syncthreads();

    int st = 0;
    for (int k0 = 16; k0 < K; k0 += 16) {
        gload(k0);          // prefetch next tile (LDGs fly during MMAs)
        compute(st);
        sstore(st ^ 1);
        __syncthreads();
        st ^= 1;
    }
    compute(st);

    // ---- epilogue
    #pragma unroll
    for (int mt = 0; mt < 4; mt++) {
        #pragma unroll
        for (int nt = 0; nt < 4; nt++) {
            const int cbase = n0 + wn * 32 + nt * 8 + tig * 2;
            #pragma unroll
            for (int e = 0; e < 4; e++) {
                const int m  = m0 + wm * 64 + mt * 16 + g + ((e >= 2) ? 8 : 0);
                const int cc = cbase + (e & 1);
                float val = acc[mt][nt][e] + bias[cc];
                if (MODE == 0) {
                    int b = m >> 11, t = m & (T_ - 1);
                    int n = cc >> 6, h = cc & 63;
                    C[(((size_t)b * NH_ + n) * T_ + t) * HD_ + h] = val;
                } else {
                    C[(size_t)m * Ncols + cc] = val;
                }
            }
        }
    }
}

// Batched QKV projection: blockIdx.z selects q / k / v
__global__ __launch_bounds__(256)
void gemm_qkv_kernel(const float* __restrict__ Aq, const float* __restrict__ Ak,
                     const float* __restrict__ Av,
                     const float* __restrict__ bq, const float* __restrict__ bk,
                     const float* __restrict__ bv,
                     float* __restrict__ Cq, float* __restrict__ Ck,
                     float* __restrict__ Cv)
{
    const int z = blockIdx.z;
    const float*    A    = (z == 0) ? Aq : (z == 1) ? Ak : Av;
    const uint32_t* Bhi  = (z == 0) ? g_wq_hi : (z == 1) ? g_wk_hi : g_wv_hi;
    const uint32_t* Blo  = (z == 0) ? g_wq_lo : (z == 1) ? g_wk_lo : g_wv_lo;
    const float*    bias = (z == 0) ? bq : (z == 1) ? bk : bv;
    float*          C    = (z == 0) ? Cq : (z == 1) ? Ck : Cv;
    gemm_core<0, false>(A, nullptr, nullptr, Bhi, Blo, bias, C, BT_, D_, NDH_);
}

__global__ __launch_bounds__(256)
void gemm_out_kernel(const float* __restrict__ bias, float* __restrict__ C)
{
    gemm_core<1, true>(nullptr, g_oh, g_ol, g_wp_hi, g_wp_lo, bias, C, BT_, NDH_, D_);
}

// ---------------------------------------------------------------------------
// tf32 tensor-core flash attention with ldmatrix fragments.
// Block = 256 threads (8 warps), 128 query rows of one (b, head); warp owns 16.
// K tile [64 key][68], V tile TRANSPOSED [64 h][68 key], P [128 q][68].
// Output: bf16 hi/lo packed pairs along (n,h) -> feeds out-proj directly.
// ---------------------------------------------------------------------------
__global__ __launch_bounds__(256, 2)
void attn_tc_kernel(const float* __restrict__ Q,
                    const float* __restrict__ K,
                    const float* __restrict__ V,
                    uint32_t* __restrict__ Ohi,
                    uint32_t* __restrict__ Olo)
{
    extern __shared__ float smx[];
    float* Kt  = smx;                 // [64][68]  K (tf32 bits), rows = key
    float* VtT = smx + 64 * 68;       // [64][68]  V^T (tf32 bits), rows = h
    float* Pw  = VtT + 64 * 68;       // [128][68] P per warp (also Q staging)

    const int tid  = threadIdx.x;
    const int warp = tid >> 5;
    const int lane = tid & 31;
    const int g    = lane >> 2;
    const int tig  = lane & 3;
    const int bn   = blockIdx.y;        // b*NH + n
    const int b    = bn / NH_;
    const int n    = bn % NH_;
    const int q0   = blockIdx.x * 128;
    const int wrow = warp * 16;         // 0..112

    const uint32_t kt_b = smaddr(Kt);
    const uint32_t vt_b = smaddr(VtT);
    const uint32_t pw_b = smaddr(Pw);

    // ldmatrix per-lane offsets (units: u32, row stride 68)
    const int arow = (lane & 7) + ((lane >> 3) & 1) * 8;
    const int ako  = (lane >> 4) * 4;
    const int brow = (lane & 7) + ((lane >> 4) & 1) * 8;
    const int bko  = ((lane >> 3) & 1) * 4;
    const uint32_t a_fo = (arow * 68 + ako) * 4;
    const uint32_t b_fo = (brow * 68 + bko) * 4;

    const float* Qg = Q + ((size_t)bn * T_ + q0) * HD_;
    const float* Kg = K + (size_t)bn * T_ * HD_;
    const float* Vg = V + (size_t)bn * T_ * HD_;

    // ---- stage Q tile (128 x 64) into Pw
    #pragma unroll
    for (int i = 0; i < 8; i++) {
        int lin = tid + i * 256;          // float4 slots over 128x16
        int r = lin >> 4, c4 = (lin & 15) << 2;
        float4 v4 = *(const float4*)(Qg + r * HD_ + c4);
        Pw[r * 68 + c4 + 0] = v4.x; Pw[r * 68 + c4 + 1] = v4.y;
        Pw[r * 68 + c4 + 2] = v4.z; Pw[r * 68 + c4 + 3] = v4.w;
    }
    __syncthreads();
    // persistent Q fragments (scaled by 1/sqrt(H) * log2(e), tf32)
    const float qs = 0.125f * 1.4426950408889634f;
    uint32_t qf[8][4];
    #pragma unroll
    for (int k8 = 0; k8 < 8; k8++) {
        uint32_t r0, r1, r2, r3;
        ldsm4(r0, r1, r2, r3, pw_b + (uint32_t)(wrow * 68 * 4) + (uint32_t)(k8 * 32) + a_fo);
        qf[k8][0] = f2tf32(__uint_as_float(r0) * qs);
        qf[k8][1] = f2tf32(__uint_as_float(r1) * qs);
        qf[k8][2] = f2tf32(__uint_as_float(r2) * qs);
        qf[k8][3] = f2tf32(__uint_as_float(r3) * qs);
    }

    float of[8][4];
    #pragma unroll
    for (int i = 0; i < 8; i++)
        #pragma unroll
        for (int e = 0; e < 4; e++) of[i][e] = 0.0f;
    float m0r = -1e30f, m1r = -1e30f;
    float l0r = 0.0f,   l1r = 0.0f;

    for (int s0 = 0; s0 < T_; s0 += 64) {
        __syncthreads();   // all warps done with Kt/VtT of previous tile
        // ---- load K -> Kt (row=key), V -> VtT (row=h, transposed)
        #pragma unroll
        for (int i = 0; i < 4; i++) {
            int lin = tid + i * 256;
            int r = lin >> 4, c4 = (lin & 15) << 2;
            float4 kv = *(const float4*)(Kg + (size_t)(s0 + r) * HD_ + c4);
            float4 vv = *(const float4*)(Vg + (size_t)(s0 + r) * HD_ + c4);
            Kt[r * 68 + c4 + 0] = __uint_as_float(f2tf32(kv.x));
            Kt[r * 68 + c4 + 1] = __uint_as_float(f2tf32(kv.y));
            Kt[r * 68 + c4 + 2] = __uint_as_float(f2tf32(kv.z));
            Kt[r * 68 + c4 + 3] = __uint_as_float(f2tf32(kv.w));
            VtT[(c4 + 0) * 68 + r] = __uint_as_float(f2tf32(vv.x));
            VtT[(c4 + 1) * 68 + r] = __uint_as_float(f2tf32(vv.y));
            VtT[(c4 + 2) * 68 + r] = __uint_as_float(f2tf32(vv.z));
            VtT[(c4 + 3) * 68 + r] = __uint_as_float(f2tf32(vv.w));
        }
        __syncthreads();

        // ---- S = (Q*qs) @ K^T ; warp computes 16x64
        float sacc[8][4];
        #pragma unroll
        for (int i = 0; i < 8; i++)
            #pragma unroll
            for (int e = 0; e < 4; e++) sacc[i][e] = 0.0f;
        #pragma unroll
        for (int k8 = 0; k8 < 8; k8++) {
            #pragma unroll
            for (int nt2 = 0; nt2 < 4; nt2++) {
                uint32_t b0a, b1a, b0b, b1b;
                ldsm4(b0a, b1a, b0b, b1b,
                      kt_b + (uint32_t)(nt2 * 16 * 68 * 4) + (uint32_t)(k8 * 32) + b_fo);
                mma_tf32(sacc[nt2*2    ], qf[k8][0], qf[k8][1], qf[k8][2], qf[k8][3], b0a, b1a);
                mma_tf32(sacc[nt2*2 + 1], qf[k8][0], qf[k8][1], qf[k8][2], qf[k8][3], b0b, b1b);
            }
        }

        // ---- online softmax (base-2)
        float mx0 = -1e30f, mx1 = -1e30f;
        #pragma unroll
        for (int nt = 0; nt < 8; nt++) {
            mx0 = fmaxf(mx0, fmaxf(sacc[nt][0], sacc[nt][1]));
            mx1 = fmaxf(mx1, fmaxf(sacc[nt][2], sacc[nt][3]));
        }
        mx0 = fmaxf(mx0, __shfl_xor_sync(0xffffffffu, mx0, 1));
        mx0 = fmaxf(mx0, __shfl_xor_sync(0xffffffffu, mx0, 2));
        mx1 = fmaxf(mx1, __shfl_xor_sync(0xffffffffu, mx1, 1));
        mx1 = fmaxf(mx1, __shfl_xor_sync(0xffffffffu, mx1, 2));
        float nm0 = fmaxf(m0r, mx0), nm1 = fmaxf(m1r, mx1);
        float cr0 = ex2(m0r - nm0), cr1 = ex2(m1r - nm1);
        m0r = nm0; m1r = nm1;

        float sum0 = 0.0f, sum1 = 0.0f;
        #pragma unroll
        for (int nt = 0; nt < 8; nt++) {
            sacc[nt][0] = ex2(sacc[nt][0] - nm0);
            sacc[nt][1] = ex2(sacc[nt][1] - nm0);
            sacc[nt][2] = ex2(sacc[nt][2] - nm1);
            sacc[nt][3] = ex2(sacc[nt][3] - nm1);
            sum0 += sacc[nt][0] + sacc[nt][1];
            sum1 += sacc[nt][2] + sacc[nt][3];
        }
        sum0 += __shfl_xor_sync(0xffffffffu, sum0, 1);
        sum0 += __shfl_xor_sync(0xffffffffu, sum0, 2);
        sum1 += __shfl_xor_sync(0xffffffffu, sum1, 1);
        sum1 += __shfl_xor_sync(0xffffffffu, sum1, 2);
        l0r = l0r * cr0 + sum0;
        l1r = l1r * cr1 + sum1;
        #pragma unroll
        for (int nt = 0; nt < 8; nt++) {
            of[nt][0] *= cr0; of[nt][1] *= cr0;
            of[nt][2] *= cr1; of[nt][3] *= cr1;
        }

        // ---- store P (tf32) into this warp's own rows of Pw
        #pragma unroll
        for (int nt = 0; nt < 8; nt++) {
            float2 v01, v23;
            v01.x = __uint_as_float(f2tf32(sacc[nt][0]));
            v01.y = __uint_as_float(f2tf32(sacc[nt][1]));
            v23.x = __uint_as_float(f2tf32(sacc[nt][2]));
            v23.y = __uint_as_float(f2tf32(sacc[nt][3]));
            *(float2*)&Pw[(wrow + g    ) * 68 + nt * 8 + tig * 2] = v01;
            *(float2*)&Pw[(wrow + g + 8) * 68 + nt * 8 + tig * 2] = v23;
        }
        __syncwarp();

        // ---- O += P @ V   (A = Pw rows of this warp, B = VtT)
        #pragma unroll
        for (int k8 = 0; k8 < 8; k8++) {
            uint32_t a0, a1, a2, a3;
            ldsm4(a0, a1, a2, a3,
                  pw_b + (uint32_t)(wrow * 68 * 4) + (uint32_t)(k8 * 32) + a_fo);
            #pragma unroll
            for (int nt2 = 0; nt2 < 4; nt2++) {
                uint32_t b0a, b1a, b0b, b1b;
                ldsm4(b0a, b1a, b0b, b1b,
                      vt_b + (uint32_t)(nt2 * 16 * 68 * 4) + (uint32_t)(k8 * 32) + b_fo);
                mma_tf32(of[nt2*2    ], a0, a1, a2, a3, b0a, b1a);
                mma_tf32(of[nt2*2 + 1], a0, a1, a2, a3, b0b, b1b);
            }
        }
    }

    // ---- epilogue: normalize, pack bf16 hi/lo pairs, write [m][(n,h)/2]
    const float inv0 = 1.0f / l0r;
    const float inv1 = 1.0f / l1r;
    const int t0 = q0 + wrow + g;
    const size_t m0row = (size_t)(b * T_ + t0) * K2_;
    const size_t m1row = (size_t)(b * T_ + t0 + 8) * K2_;
    #pragma unroll
    for (int nt = 0; nt < 8; nt++) {
        const int kp = n * 32 + nt * 4 + tig;
        uint32_t h0, l0, h1, l1;
        split2(of[nt][0] * inv0, of[nt][1] * inv0, h0, l0);
        split2(of[nt][2] * inv1, of[nt][3] * inv1, h1, l1);
        Ohi[m0row + kp] = h0;  Olo[m0row + kp] = l0;
        Ohi[m1row + kp] = h1;  Olo[m1row + kp] = l1;
    }
}

// ---------------------------------------------------------------------------
// Launch
// Inputs: 0:q 1:v 2:k 3:w_query 4:b_query 5:w_value 6:b_value 7:w_key 8:b_key
//         9:w_projection 10:b_projection
// ---------------------------------------------------------------------------
extern "C" void kernel_launch(void* const* d_in, const int* in_sizes, int n_in,
                              void* d_out, int out_size)
{
    const float* q_in = (const float*)d_in[0];
    const float* v_in = (const float*)d_in[1];
    const float* k_in = (const float*)d_in[2];
    const float* w_q  = (const float*)d_in[3];
    const float* b_q  = (const float*)d_in[4];
    const float* w_v  = (const float*)d_in[5];
    const float* b_v  = (const float*)d_in[6];
    const float* w_k  = (const float*)d_in[7];
    const float* b_k  = (const float*)d_in[8];
    const float* w_p  = (const float*)d_in[9];
    const float* b_p  = (const float*)d_in[10];
    float* out = (float*)d_out;

    float *gq, *gk, *gv;
    uint32_t *goh, *gol;
    cudaGetSymbolAddress((void**)&gq,  g_q);
    cudaGetSymbolAddress((void**)&gk,  g_k);
    cudaGetSymbolAddress((void**)&gv,  g_v);
    cudaGetSymbolAddress((void**)&goh, g_oh);
    cudaGetSymbolAddress((void**)&gol, g_ol);

    const int ATTN_SMEM = (64 * 68 + 64 * 68 + 128 * 68) * 4;   // 69632 B
    cudaFuncSetAttribute(attn_tc_kernel,
                         cudaFuncAttributeMaxDynamicSharedMemorySize, ATTN_SMEM);

    // 1. prepack weights (bf16 hi/lo pairs, [n_out][k/2] layout)
    dim3 wgrid((NDH_ * K2_) / 256, 1, 3);
    prepack_wqkv_kernel<<<wgrid, 256>>>(w_q, w_k, w_v);
    prepack_wpt_kernel<<<(D_ * K2_) / 256, 256>>>(w_p);

    // 2. QKV projections, batched in one launch (grid.z selects q/k/v)
    dim3 ggrid(NDH_ / 128, BT_ / 128, 3);   // (8, 32, 3)
    gemm_qkv_kernel<<<ggrid, 256>>>(q_in, k_in, v_in, b_q, b_k, b_v, gq, gk, gv);

    // 3. attention (tf32 flash attention, ldmatrix fragments, packed output)
    dim3 agrid(T_ / 128, B_ * NH_);         // (16, 32)
    attn_tc_kernel<<<agrid, 256, ATTN_SMEM>>>(gq, gk, gv, goh, gol);

    // 4. output projection (A prepacked by attention epilogue)
    dim3 pgrid(D_ / 128, BT_ / 128);        // (8, 32)
    gemm_out_kernel<<<pgrid, 256>>>(b_p, out);
}

// round 11
// speedup vs baseline: 1.0616x; 1.0616x over previous
#include <cuda_runtime.h>
#include <cuda_bf16.h>
#include <math.h>
#include <stdint.h>

#define B_   2
#define T_   2048
#define D_   1024
#define NH_  16
#define HD_  64
#define BT_  (B_*T_)      // 4096
#define NDH_ (NH_*HD_)    // 1024
#define K2_  (D_/2)       // 512

// Scratch (allocation-free: __device__ globals)
__device__ float g_q[(size_t)B_*NH_*T_*HD_];     // [b,n,t,h]
__device__ float g_k[(size_t)B_*NH_*T_*HD_];     // [b,n,t,h]
__device__ float g_v[(size_t)B_*NH_*T_*HD_];     // [b,n,t,h]

// attention output, prepacked bf16 hi/lo pairs along (n,h): [4096][512] u32
__device__ uint32_t g_oh[(size_t)BT_*K2_], g_ol[(size_t)BT_*K2_];

// prepacked weights: [n_out][k/2] u32 = (bf16 even-k, bf16 odd-k)
__device__ uint32_t g_wq_hi[(size_t)NDH_*K2_], g_wq_lo[(size_t)NDH_*K2_];
__device__ uint32_t g_wk_hi[(size_t)NDH_*K2_], g_wk_lo[(size_t)NDH_*K2_];
__device__ uint32_t g_wv_hi[(size_t)NDH_*K2_], g_wv_lo[(size_t)NDH_*K2_];
__device__ uint32_t g_wp_hi[(size_t)D_*K2_],   g_wp_lo[(size_t)D_*K2_];

// ---------------------------------------------------------------------------
// helpers.  ldsm4 MUST be volatile: its smem read is invisible to the
// constraint list, so without volatile the compiler hoists it across the
// __syncthreads()/stores that produce the tile (round-10 correctness bug).
// mma wrappers are pure register ops -> non-volatile so ptxas can schedule.
// ---------------------------------------------------------------------------
__device__ __forceinline__ uint32_t f2tf32(float x) {
    uint32_t r;
    asm("cvt.rna.tf32.f32 %0, %1;" : "=r"(r) : "f"(x));
    return r;
}

__device__ __forceinline__ float ex2(float x) {
    float r;
    asm("ex2.approx.f32 %0, %1;" : "=f"(r) : "f"(x));
    return r;
}

__device__ __forceinline__ uint32_t smaddr(const void* p) {
    return (uint32_t)__cvta_generic_to_shared(p);
}

__device__ __forceinline__ void ldsm4(uint32_t& r0, uint32_t& r1,
                                      uint32_t& r2, uint32_t& r3, uint32_t a) {
    asm volatile("ldmatrix.sync.aligned.m8n8.x4.shared.b16 {%0,%1,%2,%3}, [%4];"
                 : "=r"(r0), "=r"(r1), "=r"(r2), "=r"(r3) : "r"(a));
}

__device__ __forceinline__ void mma_tf32(float* c,
                                         uint32_t a0, uint32_t a1, uint32_t a2, uint32_t a3,
                                         uint32_t b0, uint32_t b1) {
    asm("mma.sync.aligned.m16n8k8.row.col.f32.tf32.tf32.f32 "
        "{%0,%1,%2,%3}, {%4,%5,%6,%7}, {%8,%9}, {%0,%1,%2,%3};"
        : "+f"(c[0]), "+f"(c[1]), "+f"(c[2]), "+f"(c[3])
        : "r"(a0), "r"(a1), "r"(a2), "r"(a3), "r"(b0), "r"(b1));
}

__device__ __forceinline__ void mma_bf16(float* c,
                                         uint32_t a0, uint32_t a1, uint32_t a2, uint32_t a3,
                                         uint32_t b0, uint32_t b1) {
    asm("mma.sync.aligned.m16n8k16.row.col.f32.bf16.bf16.f32 "
        "{%0,%1,%2,%3}, {%4,%5,%6,%7}, {%8,%9}, {%0,%1,%2,%3};"
        : "+f"(c[0]), "+f"(c[1]), "+f"(c[2]), "+f"(c[3])
        : "r"(a0), "r"(a1), "r"(a2), "r"(a3), "r"(b0), "r"(b1));
}

// split two fp32 (even,odd along k) into packed bf16x2 hi and lo parts
__device__ __forceinline__ void split2(float e, float o, uint32_t& hi, uint32_t& lo) {
    __nv_bfloat162 h = __floats2bfloat162_rn(e, o);
    float he = __low2float(h), ho = __high2float(h);
    __nv_bfloat162 l = __floats2bfloat162_rn(e - he, o - ho);
    hi = *reinterpret_cast<uint32_t*>(&h);
    lo = *reinterpret_cast<uint32_t*>(&l);
}

// ---------------------------------------------------------------------------
// Prepack QKV weights W [K][N] fp32 -> hi/lo [N][K/2] u32.  z selects q/k/v.
// ---------------------------------------------------------------------------
__global__ void prepack_wqkv_kernel(const float* __restrict__ Wq,
                                    const float* __restrict__ Wk,
                                    const float* __restrict__ Wv)
{
    const int z = blockIdx.z;
    const float* W = (z == 0) ? Wq : (z == 1) ? Wk : Wv;
    uint32_t* hi = (z == 0) ? g_wq_hi : (z == 1) ? g_wk_hi : g_wv_hi;
    uint32_t* lo = (z == 0) ? g_wq_lo : (z == 1) ? g_wk_lo : g_wv_lo;
    int idx = blockIdx.x * blockDim.x + threadIdx.x;
    if (idx >= NDH_ * K2_) return;
    int kp = idx & (K2_ - 1);
    int n  = idx >> 9;
    float e = W[(size_t)(2 * kp) * NDH_ + n];
    float o = W[(size_t)(2 * kp + 1) * NDH_ + n];
    uint32_t h, l;
    split2(e, o, h, l);
    hi[(size_t)n * K2_ + kp] = h;
    lo[(size_t)n * K2_ + kp] = l;
}

// ---------------------------------------------------------------------------
// Prepack w_projection [N, D, H] -> hi/lo [d][(n,h)/2] u32
// ---------------------------------------------------------------------------
__global__ void prepack_wpt_kernel(const float* __restrict__ wp)
{
    int idx = blockIdx.x * blockDim.x + threadIdx.x;
    if (idx >= D_ * K2_) return;
    int kp = idx & (K2_ - 1);       // n*32 + hp
    int d  = idx >> 9;
    int n  = kp >> 5;
    int hp = kp & 31;
    const float* base = wp + ((size_t)n * D_ + d) * HD_ + 2 * hp;
    float e = base[0], o = base[1];
    uint32_t h, l;
    split2(e, o, h, l);
    g_wp_hi[(size_t)d * K2_ + kp] = h;
    g_wp_lo[(size_t)d * K2_ + kp] = l;
}

// ---------------------------------------------------------------------------
// bf16-split tensor-core GEMM with ldmatrix fragments.
// A: fp32 [M,K] (APACKED=false) or hi/lo [M][K/2] u32 (APACKED=true).
// B: prepacked hi/lo [N][K/2] u32.
// 128x128 block tile, BK=16 (8 kpairs), 8 warps (2 M x 4 N), double-buffered.
// smem tiles row-major [row][kpair], row stride 12 u32 (conflict-free LDSM).
// MMAs issued variant-major (hh over all nt, then hl, then lh) so consecutive
// MMAs never share an accumulator (reuse distance 4).
// MODE 0: C -> [B, N, T, H];  MODE 1: C -> [M, Ncols] row-major.
// ---------------------------------------------------------------------------
template<int MODE, bool APACKED>
__device__ __forceinline__ void gemm_core(const float* __restrict__ A,
                                          const uint32_t* __restrict__ Ahi,
                                          const uint32_t* __restrict__ Alo,
                                          const uint32_t* __restrict__ Bhi,
                                          const uint32_t* __restrict__ Blo,
                                          const float* __restrict__ bias,
                                          float* __restrict__ C,
                                          int M, int K, int Ncols)
{
    __shared__ uint32_t AsHi[2][128 * 12];
    __shared__ uint32_t AsLo[2][128 * 12];
    __shared__ uint32_t BsHi[2][128 * 12];
    __shared__ uint32_t BsLo[2][128 * 12];

    const int tid  = threadIdx.x;
    const int warp = tid >> 5;
    const int lane = tid & 31;
    const int g    = lane >> 2;
    const int tig  = lane & 3;
    const int wm   = warp >> 2;   // 0..1  (64 rows each)
    const int wn   = warp & 3;    // 0..3  (32 cols each)
    const int m0   = blockIdx.y * 128;
    const int n0   = blockIdx.x * 128;
    const int Kp   = K >> 1;

    const int lrow  = tid >> 1;          // 0..127 (row for both A and B loads)
    const int lhalf = tid & 1;           // kpair half: 0 or 1 (4 kpairs each)

    // ldmatrix per-lane offsets (units: u32 within a row-stride-12 tile)
    const int arow = (lane & 7) + ((lane >> 3) & 1) * 8;   // A-type
    const int akp  = (lane >> 4) * 4;
    const int brow = (lane & 7) + ((lane >> 4) & 1) * 8;   // B-type
    const int bkp  = ((lane >> 3) & 1) * 4;

    const uint32_t ash = smaddr(AsHi), asl = smaddr(AsLo);
    const uint32_t bsh = smaddr(BsHi), bsl = smaddr(BsLo);
    const uint32_t a_fo = ((arow) * 12 + akp) * 4;     // fragment lane offset
    const uint32_t b_fo = ((brow) * 12 + bkp) * 4;

    float acc[4][4][4];
    #pragma unroll
    for (int i = 0; i < 4; i++)
        #pragma unroll
        for (int j = 0; j < 4; j++)
            #pragma unroll
            for (int e = 0; e < 4; e++)
                acc[i][j][e] = 0.0f;

    float4 ar0, ar1;
    uint4  arh, arl;
    uint4  brh, brl;

    auto gload = [&](int k0) {
        if (APACKED) {
            const size_t aoff = (size_t)(m0 + lrow) * Kp + (k0 >> 1) + lhalf * 4;
            arh = *(const uint4*)(Ahi + aoff);
            arl = *(const uint4*)(Alo + aoff);
        } else {
            const float4* a4 = (const float4*)(A + (size_t)(m0 + lrow) * K + k0 + lhalf * 8);
            ar0 = a4[0];
            ar1 = a4[1];
        }
        const size_t boff = (size_t)(n0 + lrow) * Kp + (k0 >> 1) + lhalf * 4;
        brh = *(const uint4*)(Bhi + boff);
        brl = *(const uint4*)(Blo + boff);
    };

    auto sstore = [&](int st) {
        const int soff = lrow * 12 + lhalf * 4;
        if (APACKED) {
            *(uint4*)&AsHi[st][soff] = arh;
            *(uint4*)&AsLo[st][soff] = arl;
        } else {
            uint4 hh, ll;
            split2(ar0.x, ar0.y, hh.x, ll.x);
            split2(ar0.z, ar0.w, hh.y, ll.y);
            split2(ar1.x, ar1.y, hh.z, ll.z);
            split2(ar1.z, ar1.w, hh.w, ll.w);
            *(uint4*)&AsHi[st][soff] = hh;
            *(uint4*)&AsLo[st][soff] = ll;
        }
        *(uint4*)&BsHi[st][soff] = brh;
        *(uint4*)&BsLo[st][soff] = brl;
    };

    auto compute = [&](int st) {
        const uint32_t sto = st * (128 * 12 * 4);
        // B fragments: 4 nt tiles via 2x (hi,lo) LDSM.x4
        uint32_t bh[4][2], bl[4][2];
        #pragma unroll
        for (int nt2 = 0; nt2 < 2; nt2++) {
            const uint32_t ro = (wn * 32 + nt2 * 16) * 12 * 4;
            ldsm4(bh[nt2*2][0], bh[nt2*2][1], bh[nt2*2+1][0], bh[nt2*2+1][1],
                  bsh + sto + ro + b_fo);
            ldsm4(bl[nt2*2][0], bl[nt2*2][1], bl[nt2*2+1][0], bl[nt2*2+1][1],
                  bsl + sto + ro + b_fo);
        }
        #pragma unroll
        for (int mt = 0; mt < 4; mt++) {
            const uint32_t ro = (wm * 64 + mt * 16) * 12 * 4;
            uint32_t ah0, ah1, ah2, ah3, al0, al1, al2, al3;
            ldsm4(ah0, ah1, ah2, ah3, ash + sto + ro + a_fo);
            ldsm4(al0, al1, al2, al3, asl + sto + ro + a_fo);
            // variant-major: consecutive MMAs hit different accumulators
            #pragma unroll
            for (int nt = 0; nt < 4; nt++)
                mma_bf16(acc[mt][nt], ah0, ah1, ah2, ah3, bh[nt][0], bh[nt][1]);
            #pragma unroll
            for (int nt = 0; nt < 4; nt++)
                mma_bf16(acc[mt][nt], ah0, ah1, ah2, ah3, bl[nt][0], bl[nt][1]);
            #pragma unroll
            for (int nt = 0; nt < 4; nt++)
                mma_bf16(acc[mt][nt], al0, al1, al2, al3, bh[nt][0], bh[nt][1]);
        }
    };

    // prologue
    gload(0);
    sstore(0);
    __syncthreads();

    int st = 0;
    for (int k0 = 16; k0 < K; k0 += 16) {
        gload(k0);          // prefetch next tile (LDGs fly during MMAs)
        compute(st);
        sstore(st ^ 1);
        __syncthreads();
        st ^= 1;
    }
    compute(st);

    // ---- epilogue
    #pragma unroll
    for (int mt = 0; mt < 4; mt++) {
        #pragma unroll
        for (int nt = 0; nt < 4; nt++) {
            const int cbase = n0 + wn * 32 + nt * 8 + tig * 2;
            #pragma unroll
            for (int e = 0; e < 4; e++) {
                const int m  = m0 + wm * 64 + mt * 16 + g + ((e >= 2) ? 8 : 0);
                const int cc = cbase + (e & 1);
                float val = acc[mt][nt][e] + bias[cc];
                if (MODE == 0) {
                    int b = m >> 11, t = m & (T_ - 1);
                    int n = cc >> 6, h = cc & 63;
                    C[(((size_t)b * NH_ + n) * T_ + t) * HD_ + h] = val;
                } else {
                    C[(size_t)m * Ncols + cc] = val;
                }
            }
        }
    }
}

// Batched QKV projection: blockIdx.z selects q / k / v
__global__ __launch_bounds__(256)
void gemm_qkv_kernel(const float* __restrict__ Aq, const float* __restrict__ Ak,
                     const float* __restrict__ Av,
                     const float* __restrict__ bq, const float* __restrict__ bk,
                     const float* __restrict__ bv,
                     float* __restrict__ Cq, float* __restrict__ Ck,
                     float* __restrict__ Cv)
{
    const int z = blockIdx.z;
    const float*    A    = (z == 0) ? Aq : (z == 1) ? Ak : Av;
    const uint32_t* Bhi  = (z == 0) ? g_wq_hi : (z == 1) ? g_wk_hi : g_wv_hi;
    const uint32_t* Blo  = (z == 0) ? g_wq_lo : (z == 1) ? g_wk_lo : g_wv_lo;
    const float*    bias = (z == 0) ? bq : (z == 1) ? bk : bv;
    float*          C    = (z == 0) ? Cq : (z == 1) ? Ck : Cv;
    gemm_core<0, false>(A, nullptr, nullptr, Bhi, Blo, bias, C, BT_, D_, NDH_);
}

__global__ __launch_bounds__(256)
void gemm_out_kernel(const float* __restrict__ bias, float* __restrict__ C)
{
    gemm_core<1, true>(nullptr, g_oh, g_ol, g_wp_hi, g_wp_lo, bias, C, BT_, NDH_, D_);
}

// ---------------------------------------------------------------------------
// tf32 tensor-core flash attention (scalar LDS fragments, non-transposed V —
// the known-good round-7 structure). Block = 256 threads (8 warps), 128 query
// rows of one (b, head); warp owns 16 rows. K/V tiles of 64 keys.
// Dynamic smem: K[64][68] + V[64][72] + P[128][68] = 70656 B -> 2 CTAs/SM.
// Epilogue emits bf16 hi/lo packed pairs -> feeds out-proj GEMM directly.
// ---------------------------------------------------------------------------
__global__ __launch_bounds__(256, 2)
void attn_tc_kernel(const float* __restrict__ Q,
                    const float* __restrict__ K,
                    const float* __restrict__ V,
                    uint32_t* __restrict__ Ohi,
                    uint32_t* __restrict__ Olo)
{
    extern __shared__ float smx[];
    float* Kt = smx;                 // [64][68] K tile (tf32 bits)
    float* Vt = smx + 64 * 68;       // [64][72] V tile (tf32 bits)
    float* Pw = Vt  + 64 * 72;       // [128][68] per-warp P (also Q staging)

    const int tid  = threadIdx.x;
    const int warp = tid >> 5;
    const int lane = tid & 31;
    const int g    = lane >> 2;
    const int tig  = lane & 3;
    const int bn   = blockIdx.y;        // b*NH + n
    const int b    = bn / NH_;
    const int n    = bn % NH_;
    const int q0   = blockIdx.x * 128;
    const int wrow = warp * 16;         // 0..112

    const float* Qg = Q + ((size_t)bn * T_ + q0) * HD_;
    const float* Kg = K + (size_t)bn * T_ * HD_;
    const float* Vg = V + (size_t)bn * T_ * HD_;

    // ---- stage Q tile (128 x 64) into Pw
    #pragma unroll
    for (int i = 0; i < 8; i++) {
        int lin = tid + i * 256;          // float4 slots over 128x16
        int r = lin >> 4, c4 = (lin & 15) << 2;
        float4 v4 = *(const float4*)(Qg + r * HD_ + c4);
        Pw[r * 68 + c4 + 0] = v4.x; Pw[r * 68 + c4 + 1] = v4.y;
        Pw[r * 68 + c4 + 2] = v4.z; Pw[r * 68 + c4 + 3] = v4.w;
    }
    __syncthreads();
    // scale folds 1/sqrt(H) and log2(e) so softmax uses raw ex2
    const float qs = 0.125f * 1.4426950408889634f;
    uint32_t qf[8][4];
    #pragma unroll
    for (int k8 = 0; k8 < 8; k8++) {
        qf[k8][0] = f2tf32(Pw[(wrow + g    ) * 68 + k8 * 8 + tig    ] * qs);
        qf[k8][1] = f2tf32(Pw[(wrow + g + 8) * 68 + k8 * 8 + tig    ] * qs);
        qf[k8][2] = f2tf32(Pw[(wrow + g    ) * 68 + k8 * 8 + tig + 4] * qs);
        qf[k8][3] = f2tf32(Pw[(wrow + g + 8) * 68 + k8 * 8 + tig + 4] * qs);
    }

    float of[8][4];
    #pragma unroll
    for (int i = 0; i < 8; i++)
        #pragma unroll
        for (int e = 0; e < 4; e++) of[i][e] = 0.0f;
    float m0r = -1e30f, m1r = -1e30f;
    float l0r = 0.0f,   l1r = 0.0f;

    for (int s0 = 0; s0 < T_; s0 += 64) {
        __syncthreads();   // all warps done with Kt/Vt of previous tile
        // ---- load K -> Kt, V -> Vt (convert to tf32); 64x16 float4 slots
        #pragma unroll
        for (int i = 0; i < 4; i++) {
            int lin = tid + i * 256;
            int r = lin >> 4, c4 = (lin & 15) << 2;
            float4 kv = *(const float4*)(Kg + (size_t)(s0 + r) * HD_ + c4);
            float4 vv = *(const float4*)(Vg + (size_t)(s0 + r) * HD_ + c4);
            Kt[r * 68 + c4 + 0] = __uint_as_float(f2tf32(kv.x));
            Kt[r * 68 + c4 + 1] = __uint_as_float(f2tf32(kv.y));
            Kt[r * 68 + c4 + 2] = __uint_as_float(f2tf32(kv.z));
            Kt[r * 68 + c4 + 3] = __uint_as_float(f2tf32(kv.w));
            Vt[r * 72 + c4 + 0] = __uint_as_float(f2tf32(vv.x));
            Vt[r * 72 + c4 + 1] = __uint_as_float(f2tf32(vv.y));
            Vt[r * 72 + c4 + 2] = __uint_as_float(f2tf32(vv.z));
            Vt[r * 72 + c4 + 3] = __uint_as_float(f2tf32(vv.w));
        }
        __syncthreads();

        // ---- S = (Q*qs) @ K^T ; warp computes 16x64
        float sacc[8][4];
        #pragma unroll
        for (int i = 0; i < 8; i++)
            #pragma unroll
            for (int e = 0; e < 4; e++) sacc[i][e] = 0.0f;
        #pragma unroll
        for (int k8 = 0; k8 < 8; k8++) {
            #pragma unroll
            for (int nt = 0; nt < 8; nt++) {
                uint32_t b0 = __float_as_uint(Kt[(nt * 8 + g) * 68 + k8 * 8 + tig    ]);
                uint32_t b1 = __float_as_uint(Kt[(nt * 8 + g) * 68 + k8 * 8 + tig + 4]);
                mma_tf32(sacc[nt], qf[k8][0], qf[k8][1], qf[k8][2], qf[k8][3], b0, b1);
            }
        }

        // ---- online softmax (base-2)
        float mx0 = -1e30f, mx1 = -1e30f;
        #pragma unroll
        for (int nt = 0; nt < 8; nt++) {
            mx0 = fmaxf(mx0, fmaxf(sacc[nt][0], sacc[nt][1]));
            mx1 = fmaxf(mx1, fmaxf(sacc[nt][2], sacc[nt][3]));
        }
        mx0 = fmaxf(mx0, __shfl_xor_sync(0xffffffffu, mx0, 1));
        mx0 = fmaxf(mx0, __shfl_xor_sync(0xffffffffu, mx0, 2));
        mx1 = fmaxf(mx1, __shfl_xor_sync(0xffffffffu, mx1, 1));
        mx1 = fmaxf(mx1, __shfl_xor_sync(0xffffffffu, mx1, 2));
        float nm0 = fmaxf(m0r, mx0), nm1 = fmaxf(m1r, mx1);
        float cr0 = ex2(m0r - nm0), cr1 = ex2(m1r - nm1);
        m0r = nm0; m1r = nm1;

        float sum0 = 0.0f, sum1 = 0.0f;
        #pragma unroll
        for (int nt = 0; nt < 8; nt++) {
            sacc[nt][0] = ex2(sacc[nt][0] - nm0);
            sacc[nt][1] = ex2(sacc[nt][1] - nm0);
            sacc[nt][2] = ex2(sacc[nt][2] - nm1);
            sacc[nt][3] = ex2(sacc[nt][3] - nm1);
            sum0 += sacc[nt][0] + sacc[nt][1];
            sum1 += sacc[nt][2] + sacc[nt][3];
        }
        sum0 += __shfl_xor_sync(0xffffffffu, sum0, 1);
        sum0 += __shfl_xor_sync(0xffffffffu, sum0, 2);
        sum1 += __shfl_xor_sync(0xffffffffu, sum1, 1);
        sum1 += __shfl_xor_sync(0xffffffffu, sum1, 2);
        l0r = l0r * cr0 + sum0;
        l1r = l1r * cr1 + sum1;
        #pragma unroll
        for (int nt = 0; nt < 8; nt++) {
            of[nt][0] *= cr0; of[nt][1] *= cr0;
            of[nt][2] *= cr1; of[nt][3] *= cr1;
        }

        // ---- store P (tf32) into this warp's own rows of Pw
        #pragma unroll
        for (int nt = 0; nt < 8; nt++) {
            float2 v01, v23;
            v01.x = __uint_as_float(f2tf32(sacc[nt][0]));
            v01.y = __uint_as_float(f2tf32(sacc[nt][1]));
            v23.x = __uint_as_float(f2tf32(sacc[nt][2]));
            v23.y = __uint_as_float(f2tf32(sacc[nt][3]));
            *(float2*)&Pw[(wrow + g    ) * 68 + nt * 8 + tig * 2] = v01;
            *(float2*)&Pw[(wrow + g + 8) * 68 + nt * 8 + tig * 2] = v23;
        }
        __syncwarp();

        // ---- O += P @ V
        #pragma unroll
        for (int k8 = 0; k8 < 8; k8++) {
            uint32_t a0 = __float_as_uint(Pw[(wrow + g    ) * 68 + k8 * 8 + tig    ]);
            uint32_t a1 = __float_as_uint(Pw[(wrow + g + 8) * 68 + k8 * 8 + tig    ]);
            uint32_t a2 = __float_as_uint(Pw[(wrow + g    ) * 68 + k8 * 8 + tig + 4]);
            uint32_t a3 = __float_as_uint(Pw[(wrow + g + 8) * 68 + k8 * 8 + tig + 4]);
            #pragma unroll
            for (int nt = 0; nt < 8; nt++) {
                uint32_t b0 = __float_as_uint(Vt[(k8 * 8 + tig    ) * 72 + nt * 8 + g]);
                uint32_t b1 = __float_as_uint(Vt[(k8 * 8 + tig + 4) * 72 + nt * 8 + g]);
                mma_tf32(of[nt], a0, a1, a2, a3, b0, b1);
            }
        }
    }

    // ---- epilogue: normalize, pack bf16 hi/lo pairs, write [m][(n,h)/2]
    const float inv0 = 1.0f / l0r;
    const float inv1 = 1.0f / l1r;
    const int t0 = q0 + wrow + g;
    const size_t m0row = (size_t)(b * T_ + t0) * K2_;
    const size_t m1row = (size_t)(b * T_ + t0 + 8) * K2_;
    #pragma unroll
    for (int nt = 0; nt < 8; nt++) {
        const int kp = n * 32 + nt * 4 + tig;
        uint32_t h0, l0, h1, l1;
        split2(of[nt][0] * inv0, of[nt][1] * inv0, h0, l0);
        split2(of[nt][2] * inv1, of[nt][3] * inv1, h1, l1);
        Ohi[m0row + kp] = h0;  Olo[m0row + kp] = l0;
        Ohi[m1row + kp] = h1;  Olo[m1row + kp] = l1;
    }
}

// ---------------------------------------------------------------------------
// Launch
// Inputs: 0:q 1:v 2:k 3:w_query 4:b_query 5:w_value 6:b_value 7:w_key 8:b_key
//         9:w_projection 10:b_projection
// ---------------------------------------------------------------------------
extern "C" void kernel_launch(void* const* d_in, const int* in_sizes, int n_in,
                              void* d_out, int out_size)
{
    const float* q_in = (const float*)d_in[0];
    const float* v_in = (const float*)d_in[1];
    const float* k_in = (const float*)d_in[2];
    const float* w_q  = (const float*)d_in[3];
    const float* b_q  = (const float*)d_in[4];
    const float* w_v  = (const float*)d_in[5];
    const float* b_v  = (const float*)d_in[6];
    const float* w_k  = (const float*)d_in[7];
    const float* b_k  = (const float*)d_in[8];
    const float* w_p  = (const float*)d_in[9];
    const float* b_p  = (const float*)d_in[10];
    float* out = (float*)d_out;

    float *gq, *gk, *gv;
    uint32_t *goh, *gol;
    cudaGetSymbolAddress((void**)&gq,  g_q);
    cudaGetSymbolAddress((void**)&gk,  g_k);
    cudaGetSymbolAddress((void**)&gv,  g_v);
    cudaGetSymbolAddress((void**)&goh, g_oh);
    cudaGetSymbolAddress((void**)&gol, g_ol);

    const int ATTN_SMEM = (64 * 68 + 64 * 72 + 128 * 68) * 4;   // 70656 B
    cudaFuncSetAttribute(attn_tc_kernel,
                         cudaFuncAttributeMaxDynamicSharedMemorySize, ATTN_SMEM);

    // 1. prepack weights (bf16 hi/lo pairs, [n_out][k/2] layout)
    dim3 wgrid((NDH_ * K2_) / 256, 1, 3);
    prepack_wqkv_kernel<<<wgrid, 256>>>(w_q, w_k, w_v);
    prepack_wpt_kernel<<<(D_ * K2_) / 256, 256>>>(w_p);

    // 2. QKV projections, batched in one launch (grid.z selects q/k/v)
    dim3 ggrid(NDH_ / 128, BT_ / 128, 3);   // (8, 32, 3)
    gemm_qkv_kernel<<<ggrid, 256>>>(q_in, k_in, v_in, b_q, b_k, b_v, gq, gk, gv);

    // 3. attention (tf32 flash attention, packed bf16 output)
    dim3 agrid(T_ / 128, B_ * NH_);         // (16, 32)
    attn_tc_kernel<<<agrid, 256, ATTN_SMEM>>>(gq, gk, gv, goh, gol);

    // 4. output projection (A prepacked by attention epilogue)
    dim3 pgrid(D_ / 128, BT_ / 128);        // (8, 32)
    gemm_out_kernel<<<pgrid, 256>>>(b_p, out);
}